// round 1
// baseline (speedup 1.0000x reference)
#include <cuda_runtime.h>
#include <cuda_bf16.h>
#include <math.h>

// Problem constants: B=4, S=2048, D=1024, H=2048, O=1024, E=8, K=2
#define TB   8192      // tokens = B*S
#define DD   1024
#define HH   2048
#define OO   1024
#define NE   8
#define NR   16384     // total routed rows = TB*K

// ---------------- scratch (__device__ globals; no allocation) ----------------
__device__ int   g_cnt[NE];
__device__ int   g_off[NE];
__device__ int   g_fill[NE];
__device__ int   g_tok_e[TB * 2];
__device__ float g_tok_p[TB * 2];
__device__ int   g_row_tok[NR];
__device__ float g_row_gate[NR];
__device__ int   g_tok_row[TB * 2];
__device__ float g_hbuf[(size_t)NR * HH];   // 134 MB: expert-hidden activations
__device__ float g_comb[(size_t)NR * OO];   // 67 MB: per-row expert outputs (gate-scaled)

// ---------------- kernel 0: zero counters ----------------
__global__ void zero_kernel() {
    int i = threadIdx.x;
    if (i < NE) { g_cnt[i] = 0; g_fill[i] = 0; }
}

// ---------------- kernel 1: gate (logits -> softmax -> top2) ----------------
__global__ __launch_bounds__(256) void gate_kernel(
    const float* __restrict__ x, const float* __restrict__ gw,
    const float* __restrict__ gb)
{
    int t   = blockIdx.x;
    int tid = threadIdx.x;
    int w   = tid >> 5, lane = tid & 31;   // 8 warps = 8 experts
    const float* xr = x + (size_t)t * DD;
    const float* gr = gw + (size_t)w * DD;
    float s = 0.f;
    #pragma unroll 8
    for (int j = lane; j < DD; j += 32) s += xr[j] * gr[j];
    #pragma unroll
    for (int o = 16; o > 0; o >>= 1) s += __shfl_xor_sync(0xFFFFFFFFu, s, o);

    __shared__ float lg[NE];
    if (lane == 0) lg[w] = s + gb[w];
    __syncthreads();

    if (tid == 0) {
        float mx = lg[0];
        #pragma unroll
        for (int e = 1; e < NE; e++) mx = fmaxf(mx, lg[e]);
        float ex[NE]; float den = 0.f;
        #pragma unroll
        for (int e = 0; e < NE; e++) { ex[e] = expf(lg[e] - mx); den += ex[e]; }
        // top-1 (first index on tie, matching jax top_k)
        int i0 = 0;
        #pragma unroll
        for (int e = 1; e < NE; e++) if (lg[e] > lg[i0]) i0 = e;
        // top-2
        int i1 = (i0 == 0) ? 1 : 0;
        #pragma unroll
        for (int e = 0; e < NE; e++)
            if (e != i0 && e != i1 && lg[e] > lg[i1]) i1 = e;
        float inv = 1.f / den;
        g_tok_e[t * 2 + 0] = i0;  g_tok_p[t * 2 + 0] = ex[i0] * inv;
        g_tok_e[t * 2 + 1] = i1;  g_tok_p[t * 2 + 1] = ex[i1] * inv;
        atomicAdd(&g_cnt[i0], 1);
        atomicAdd(&g_cnt[i1], 1);
    }
}

// ---------------- kernel 2: exclusive scan over 8 counts ----------------
__global__ void offsets_kernel() {
    if (threadIdx.x == 0) {
        int s = 0;
        #pragma unroll
        for (int e = 0; e < NE; e++) { g_off[e] = s; s += g_cnt[e]; }
    }
}

// ---------------- kernel 3: scatter tokens into compact per-expert rows ----
__global__ void scatter_kernel() {
    int t = blockIdx.x * blockDim.x + threadIdx.x;
    if (t >= TB) return;
    #pragma unroll
    for (int k = 0; k < 2; k++) {
        int e   = g_tok_e[t * 2 + k];
        int pos = atomicAdd(&g_fill[e], 1);
        int r   = g_off[e] + pos;
        g_row_tok[r]  = t;
        g_row_gate[r] = g_tok_p[t * 2 + k];
        g_tok_row[t * 2 + k] = r;
    }
}

// ---------------- GEMM1: hbuf = relu(gather(x) @ w1[e] + b1[e]) ------------
// 128x128 tile, 256 threads, 8x8 micro-tile, K-step 16.
__global__ __launch_bounds__(256) void gemm1_kernel(
    const float* __restrict__ x, const float* __restrict__ w1,
    const float* __restrict__ b1)
{
    int e   = blockIdx.z;
    int cnt = g_cnt[e];
    int m0  = blockIdx.y * 128;
    if (m0 >= cnt) return;
    int n0   = blockIdx.x * 128;
    int base = g_off[e];

    __shared__ float As[16][128];
    __shared__ float Bs[16][128];
    __shared__ int   toks[128];

    int tid = threadIdx.x;
    if (tid < 128) {
        int m = m0 + tid;
        toks[tid] = g_row_tok[base + ((m < cnt) ? m : 0)];
    }
    __syncthreads();

    const float* Bp = w1 + (size_t)e * DD * HH + n0;
    int tx = tid & 15, ty = tid >> 4;

    float acc[8][8];
    #pragma unroll
    for (int i = 0; i < 8; i++)
        #pragma unroll
        for (int j = 0; j < 8; j++) acc[i][j] = 0.f;

    for (int k0 = 0; k0 < DD; k0 += 16) {
        // A: 128 rows x 16 k  (gathered) -> 512 float4, 2 per thread
        #pragma unroll
        for (int l = 0; l < 2; l++) {
            int flat = l * 256 + tid;
            int q = flat >> 7, m = flat & 127;     // q: which float4 of 16 k
            float4 v = *(const float4*)(x + (size_t)toks[m] * DD + k0 + q * 4);
            As[q * 4 + 0][m] = v.x; As[q * 4 + 1][m] = v.y;
            As[q * 4 + 2][m] = v.z; As[q * 4 + 3][m] = v.w;
        }
        // B: 16 k x 128 n (coalesced)
        #pragma unroll
        for (int l = 0; l < 2; l++) {
            int flat = l * 256 + tid;
            int kk = flat >> 5, nq = flat & 31;
            *(float4*)&Bs[kk][nq * 4] =
                *(const float4*)(Bp + (size_t)(k0 + kk) * HH + nq * 4);
        }
        __syncthreads();
        #pragma unroll
        for (int kk = 0; kk < 16; kk++) {
            float4 a0 = *(const float4*)&As[kk][ty * 8];
            float4 a1 = *(const float4*)&As[kk][ty * 8 + 4];
            float4 b0 = *(const float4*)&Bs[kk][tx * 8];
            float4 b1v = *(const float4*)&Bs[kk][tx * 8 + 4];
            float a[8] = {a0.x,a0.y,a0.z,a0.w,a1.x,a1.y,a1.z,a1.w};
            float b[8] = {b0.x,b0.y,b0.z,b0.w,b1v.x,b1v.y,b1v.z,b1v.w};
            #pragma unroll
            for (int i = 0; i < 8; i++)
                #pragma unroll
                for (int j = 0; j < 8; j++)
                    acc[i][j] = fmaf(a[i], b[j], acc[i][j]);
        }
        __syncthreads();
    }

    // epilogue: +bias, relu, store hbuf
    float bv[8];
    {
        float4 v0 = *(const float4*)(b1 + (size_t)e * HH + n0 + tx * 8);
        float4 v1 = *(const float4*)(b1 + (size_t)e * HH + n0 + tx * 8 + 4);
        bv[0]=v0.x; bv[1]=v0.y; bv[2]=v0.z; bv[3]=v0.w;
        bv[4]=v1.x; bv[5]=v1.y; bv[6]=v1.z; bv[7]=v1.w;
    }
    #pragma unroll
    for (int i = 0; i < 8; i++) {
        int m = m0 + ty * 8 + i;
        if (m < cnt) {
            float* dst = g_hbuf + (size_t)(base + m) * HH + n0 + tx * 8;
            float4 v0 = make_float4(fmaxf(acc[i][0]+bv[0],0.f), fmaxf(acc[i][1]+bv[1],0.f),
                                    fmaxf(acc[i][2]+bv[2],0.f), fmaxf(acc[i][3]+bv[3],0.f));
            float4 v1 = make_float4(fmaxf(acc[i][4]+bv[4],0.f), fmaxf(acc[i][5]+bv[5],0.f),
                                    fmaxf(acc[i][6]+bv[6],0.f), fmaxf(acc[i][7]+bv[7],0.f));
            *(float4*)dst       = v0;
            *(float4*)(dst + 4) = v1;
        }
    }
}

// ---------------- GEMM2: comb = (hbuf @ w2[e] + b2[e]) * gate ---------------
__global__ __launch_bounds__(256) void gemm2_kernel(
    const float* __restrict__ w2, const float* __restrict__ b2)
{
    int e   = blockIdx.z;
    int cnt = g_cnt[e];
    int m0  = blockIdx.y * 128;
    if (m0 >= cnt) return;
    int n0   = blockIdx.x * 128;
    int base = g_off[e];

    __shared__ float As[16][128];
    __shared__ float Bs[16][128];

    int tid = threadIdx.x;
    const float* Bp = w2 + (size_t)e * HH * OO + n0;
    int tx = tid & 15, ty = tid >> 4;

    // precompute clamped hbuf row for A loads (2 per thread, k-invariant)
    int rA[2]; int qA[2];
    #pragma unroll
    for (int l = 0; l < 2; l++) {
        int flat = l * 256 + tid;
        int m = flat & 127;
        qA[l] = flat >> 7;
        int mm = m0 + m; if (mm >= cnt) mm = cnt - 1;
        rA[l] = base + mm;
    }

    float acc[8][8];
    #pragma unroll
    for (int i = 0; i < 8; i++)
        #pragma unroll
        for (int j = 0; j < 8; j++) acc[i][j] = 0.f;

    for (int k0 = 0; k0 < HH; k0 += 16) {
        #pragma unroll
        for (int l = 0; l < 2; l++) {
            int flat = l * 256 + tid;
            int m = flat & 127;
            float4 v = *(const float4*)(g_hbuf + (size_t)rA[l] * HH + k0 + qA[l] * 4);
            As[qA[l] * 4 + 0][m] = v.x; As[qA[l] * 4 + 1][m] = v.y;
            As[qA[l] * 4 + 2][m] = v.z; As[qA[l] * 4 + 3][m] = v.w;
        }
        #pragma unroll
        for (int l = 0; l < 2; l++) {
            int flat = l * 256 + tid;
            int kk = flat >> 5, nq = flat & 31;
            *(float4*)&Bs[kk][nq * 4] =
                *(const float4*)(Bp + (size_t)(k0 + kk) * OO + nq * 4);
        }
        __syncthreads();
        #pragma unroll
        for (int kk = 0; kk < 16; kk++) {
            float4 a0 = *(const float4*)&As[kk][ty * 8];
            float4 a1 = *(const float4*)&As[kk][ty * 8 + 4];
            float4 b0 = *(const float4*)&Bs[kk][tx * 8];
            float4 b1v = *(const float4*)&Bs[kk][tx * 8 + 4];
            float a[8] = {a0.x,a0.y,a0.z,a0.w,a1.x,a1.y,a1.z,a1.w};
            float b[8] = {b0.x,b0.y,b0.z,b0.w,b1v.x,b1v.y,b1v.z,b1v.w};
            #pragma unroll
            for (int i = 0; i < 8; i++)
                #pragma unroll
                for (int j = 0; j < 8; j++)
                    acc[i][j] = fmaf(a[i], b[j], acc[i][j]);
        }
        __syncthreads();
    }

    float bv[8];
    {
        float4 v0 = *(const float4*)(b2 + (size_t)e * OO + n0 + tx * 8);
        float4 v1 = *(const float4*)(b2 + (size_t)e * OO + n0 + tx * 8 + 4);
        bv[0]=v0.x; bv[1]=v0.y; bv[2]=v0.z; bv[3]=v0.w;
        bv[4]=v1.x; bv[5]=v1.y; bv[6]=v1.z; bv[7]=v1.w;
    }
    #pragma unroll
    for (int i = 0; i < 8; i++) {
        int m = m0 + ty * 8 + i;
        if (m < cnt) {
            int r = base + m;
            float g = g_row_gate[r];
            float* dst = g_comb + (size_t)r * OO + n0 + tx * 8;
            float4 v0 = make_float4((acc[i][0]+bv[0])*g, (acc[i][1]+bv[1])*g,
                                    (acc[i][2]+bv[2])*g, (acc[i][3]+bv[3])*g);
            float4 v1 = make_float4((acc[i][4]+bv[4])*g, (acc[i][5]+bv[5])*g,
                                    (acc[i][6]+bv[6])*g, (acc[i][7]+bv[7])*g);
            *(float4*)dst       = v0;
            *(float4*)(dst + 4) = v1;
        }
    }
}

// ---------------- combine: out[t] = comb[row0(t)] + comb[row1(t)] -----------
__global__ __launch_bounds__(256) void combine_kernel(float* __restrict__ out) {
    int idx = blockIdx.x * blockDim.x + threadIdx.x;   // float4 index
    const int total = TB * OO / 4;
    if (idx >= total) return;
    int t = idx / (OO / 4);
    int c = (idx % (OO / 4)) * 4;
    int r0 = g_tok_row[t * 2 + 0];
    int r1 = g_tok_row[t * 2 + 1];
    float4 a = *(const float4*)(g_comb + (size_t)r0 * OO + c);
    float4 b = *(const float4*)(g_comb + (size_t)r1 * OO + c);
    float4 o = make_float4(a.x + b.x, a.y + b.y, a.z + b.z, a.w + b.w);
    *(float4*)(out + (size_t)t * OO + c) = o;
}

// ---------------- launch ----------------------------------------------------
extern "C" void kernel_launch(void* const* d_in, const int* in_sizes, int n_in,
                              void* d_out, int out_size)
{
    const float* x   = (const float*)d_in[0];
    const float* gw  = (const float*)d_in[1];
    const float* gb  = (const float*)d_in[2];
    const float* w1  = (const float*)d_in[3];
    const float* b1  = (const float*)d_in[4];
    const float* w2  = (const float*)d_in[5];
    const float* b2  = (const float*)d_in[6];
    float* out = (float*)d_out;

    zero_kernel<<<1, 32>>>();
    gate_kernel<<<TB, 256>>>(x, gw, gb);
    offsets_kernel<<<1, 1>>>();
    scatter_kernel<<<TB / 256, 256>>>();
    gemm1_kernel<<<dim3(HH / 128, 64, NE), 256>>>(x, w1, b1);
    gemm2_kernel<<<dim3(OO / 128, 64, NE), 256>>>(w2, b2);
    combine_kernel<<<(TB * OO / 4 + 255) / 256, 256>>>(out);
}

// round 10
// speedup vs baseline: 3.1973x; 3.1973x over previous
#include <cuda_runtime.h>
#include <cuda_fp16.h>
#include <mma.h>
#include <math.h>
#include <stdint.h>

using namespace nvcuda;

// Problem constants: B=4, S=2048, D=1024, H=2048, O=1024, E=8, K=2
#define TB   8192
#define DD   1024
#define HH   2048
#define OO   1024
#define NE   8
#define NR   16384

// ---------------- scratch (__device__ globals) — all fp32, as in passing R1 --
__device__ int    g_cnt[NE];
__device__ int    g_off[NE];
__device__ int    g_fill[NE];
__device__ int    g_tok_e[TB * 2];
__device__ float  g_tok_p[TB * 2];
__device__ int    g_row_tok[NR];
__device__ float  g_row_gate[NR];
__device__ int    g_tok_row[TB * 2];
__device__ float  g_hbuf[(size_t)NR * HH];   // 134 MB hidden activations (fp32)
__device__ float  g_comb[(size_t)NR * OO];   // 67 MB  per-row outputs (gated)

// smem geometry
#define ROWP   40            // A row pitch (halves): 32 data + 8 pad
#define BROWP  136           // B row pitch (halves): 128 data + 8 pad
#define KC     32

// ---------------- small kernels (identical to passing R1) ----------------
__global__ void zero_kernel() {
    int i = threadIdx.x;
    if (i < NE) { g_cnt[i] = 0; g_fill[i] = 0; }
}

__global__ __launch_bounds__(256) void gate_kernel(
    const float* __restrict__ x, const float* __restrict__ gw, const float* __restrict__ gb)
{
    int t = blockIdx.x, tid = threadIdx.x;
    int w = tid >> 5, lane = tid & 31;
    const float* xr = x + (size_t)t * DD;
    const float* gr = gw + (size_t)w * DD;
    float s = 0.f;
    #pragma unroll 8
    for (int j = lane; j < DD; j += 32) s += xr[j] * gr[j];
    #pragma unroll
    for (int o = 16; o > 0; o >>= 1) s += __shfl_xor_sync(0xFFFFFFFFu, s, o);
    __shared__ float lg[NE];
    if (lane == 0) lg[w] = s + gb[w];
    __syncthreads();
    if (tid == 0) {
        float mx = lg[0];
        #pragma unroll
        for (int e = 1; e < NE; e++) mx = fmaxf(mx, lg[e]);
        float ex[NE]; float den = 0.f;
        #pragma unroll
        for (int e = 0; e < NE; e++) { ex[e] = expf(lg[e] - mx); den += ex[e]; }
        int i0 = 0;
        #pragma unroll
        for (int e = 1; e < NE; e++) if (lg[e] > lg[i0]) i0 = e;
        int i1 = (i0 == 0) ? 1 : 0;
        #pragma unroll
        for (int e = 0; e < NE; e++) if (e != i0 && e != i1 && lg[e] > lg[i1]) i1 = e;
        float inv = 1.f / den;
        g_tok_e[t * 2 + 0] = i0; g_tok_p[t * 2 + 0] = ex[i0] * inv;
        g_tok_e[t * 2 + 1] = i1; g_tok_p[t * 2 + 1] = ex[i1] * inv;
        atomicAdd(&g_cnt[i0], 1);
        atomicAdd(&g_cnt[i1], 1);
    }
}

__global__ void offsets_kernel() {
    if (threadIdx.x == 0) {
        int s = 0;
        #pragma unroll
        for (int e = 0; e < NE; e++) { g_off[e] = s; s += g_cnt[e]; }
    }
}

__global__ void scatter_kernel() {
    int t = blockIdx.x * blockDim.x + threadIdx.x;
    if (t >= TB) return;
    #pragma unroll
    for (int k = 0; k < 2; k++) {
        int e = g_tok_e[t * 2 + k];
        int pos = atomicAdd(&g_fill[e], 1);
        int r = g_off[e] + pos;
        g_row_tok[r] = t;
        g_row_gate[r] = g_tok_p[t * 2 + k];
        g_tok_row[t * 2 + k] = r;
    }
}

// ---------------- fused-convert WMMA GEMM core ------------------------------
// CTA tile 128x128, KC=32, double-buffered smem, 8 warps (4m x 2n: warp 32x64).
// A: rows gathered from fp32 src (stride sk), converted fp16 in-kernel.
// B: weight [k][n] row-major fp32 (stride sn), converted fp16 in-kernel.
// Epilogue via functor flag: relu+store-fp32-hbuf (G1) or bias+gate (G2).

template<int SK, int NCHUNKS, bool RELU>
__device__ __forceinline__ void gemm_body(
    const float* __restrict__ Asrc_base,   // base of A matrix (x or hbuf)
    const int*   srcrow,                   // smem row list [128] (token or hbuf row)
    const float* __restrict__ Bsrc,        // &w[e][0][n0]  (stride SN per k)
    int SN,
    __half* Ab0, __half* Ab1, __half* Bb0, __half* Bb1,
    float* accout /*8 warps x 2 x 4 handled by caller*/,
    int tid,
    wmma::fragment<wmma::accumulator, 16, 16, 16, float> (&acc)[2][4])
{
    int wid = tid >> 5;
    int warp_m = wid >> 1, warp_n = wid & 1;

    // A fill mapping: row = tid>>1 (0..127), q = tid&1 (16 floats each)
    int arow = tid >> 1, aq = tid & 1;
    const float* Ag = Asrc_base + (size_t)srcrow[arow] * SK + aq * 16;
    __half* Asl0 = Ab0 + arow * ROWP + aq * 16;
    __half* Asl1 = Ab1 + arow * ROWP + aq * 16;
    // B fill mapping: krow = tid>>3 (0..31), q = tid&7 (16 floats each)
    int brow = tid >> 3, bq = tid & 7;
    const float* Bg = Bsrc + (size_t)brow * SN + bq * 16;
    __half* Bsl0 = Bb0 + brow * BROWP + bq * 16;
    __half* Bsl1 = Bb1 + brow * BROWP + bq * 16;

    // chunk 0 fill
    {
        float4 v0 = *(const float4*)(Ag);
        float4 v1 = *(const float4*)(Ag + 4);
        float4 v2 = *(const float4*)(Ag + 8);
        float4 v3 = *(const float4*)(Ag + 12);
        __half h[16] = {
            __float2half_rn(v0.x), __float2half_rn(v0.y), __float2half_rn(v0.z), __float2half_rn(v0.w),
            __float2half_rn(v1.x), __float2half_rn(v1.y), __float2half_rn(v1.z), __float2half_rn(v1.w),
            __float2half_rn(v2.x), __float2half_rn(v2.y), __float2half_rn(v2.z), __float2half_rn(v2.w),
            __float2half_rn(v3.x), __float2half_rn(v3.y), __float2half_rn(v3.z), __float2half_rn(v3.w) };
        *(uint4*)(Asl0)     = ((uint4*)h)[0];
        *(uint4*)(Asl0 + 8) = ((uint4*)h)[1];
        float4 w0 = *(const float4*)(Bg);
        float4 w1v = *(const float4*)(Bg + 4);
        float4 w2v = *(const float4*)(Bg + 8);
        float4 w3 = *(const float4*)(Bg + 12);
        __half g[16] = {
            __float2half_rn(w0.x), __float2half_rn(w0.y), __float2half_rn(w0.z), __float2half_rn(w0.w),
            __float2half_rn(w1v.x), __float2half_rn(w1v.y), __float2half_rn(w1v.z), __float2half_rn(w1v.w),
            __float2half_rn(w2v.x), __float2half_rn(w2v.y), __float2half_rn(w2v.z), __float2half_rn(w2v.w),
            __float2half_rn(w3.x), __float2half_rn(w3.y), __float2half_rn(w3.z), __float2half_rn(w3.w) };
        *(uint4*)(Bsl0)     = ((uint4*)g)[0];
        *(uint4*)(Bsl0 + 8) = ((uint4*)g)[1];
    }
    __syncthreads();

    for (int ch = 0; ch < NCHUNKS; ch++) {
        // prefetch next chunk into registers
        float4 v0, v1, v2, v3, w0, w1v, w2v, w3;
        if (ch + 1 < NCHUNKS) {
            const float* An = Ag + (ch + 1) * KC;
            const float* Bn = Bg + (size_t)(ch + 1) * KC * SN;
            v0 = *(const float4*)(An);      v1 = *(const float4*)(An + 4);
            v2 = *(const float4*)(An + 8);  v3 = *(const float4*)(An + 12);
            w0 = *(const float4*)(Bn);      w1v = *(const float4*)(Bn + 4);
            w2v = *(const float4*)(Bn + 8); w3 = *(const float4*)(Bn + 12);
        }
        const __half* Ac = (ch & 1) ? Ab1 : Ab0;
        const __half* Bc = (ch & 1) ? Bb1 : Bb0;
        #pragma unroll
        for (int kf = 0; kf < KC; kf += 16) {
            wmma::fragment<wmma::matrix_a, 16, 16, 16, __half, wmma::row_major> af[2];
            wmma::fragment<wmma::matrix_b, 16, 16, 16, __half, wmma::row_major> bf[4];
            #pragma unroll
            for (int i = 0; i < 2; i++)
                wmma::load_matrix_sync(af[i], Ac + (warp_m * 32 + i * 16) * ROWP + kf, ROWP);
            #pragma unroll
            for (int j = 0; j < 4; j++)
                wmma::load_matrix_sync(bf[j], Bc + kf * BROWP + warp_n * 64 + j * 16, BROWP);
            #pragma unroll
            for (int i = 0; i < 2; i++)
                #pragma unroll
                for (int j = 0; j < 4; j++)
                    wmma::mma_sync(acc[i][j], af[i], bf[j], acc[i][j]);
        }
        __syncthreads();
        if (ch + 1 < NCHUNKS) {
            __half* Asl = (ch & 1) ? Asl0 : Asl1;
            __half* Bsl = (ch & 1) ? Bsl0 : Bsl1;
            __half h[16] = {
                __float2half_rn(v0.x), __float2half_rn(v0.y), __float2half_rn(v0.z), __float2half_rn(v0.w),
                __float2half_rn(v1.x), __float2half_rn(v1.y), __float2half_rn(v1.z), __float2half_rn(v1.w),
                __float2half_rn(v2.x), __float2half_rn(v2.y), __float2half_rn(v2.z), __float2half_rn(v2.w),
                __float2half_rn(v3.x), __float2half_rn(v3.y), __float2half_rn(v3.z), __float2half_rn(v3.w) };
            *(uint4*)(Asl)     = ((uint4*)h)[0];
            *(uint4*)(Asl + 8) = ((uint4*)h)[1];
            __half g[16] = {
                __float2half_rn(w0.x), __float2half_rn(w0.y), __float2half_rn(w0.z), __float2half_rn(w0.w),
                __float2half_rn(w1v.x), __float2half_rn(w1v.y), __float2half_rn(w1v.z), __float2half_rn(w1v.w),
                __float2half_rn(w2v.x), __float2half_rn(w2v.y), __float2half_rn(w2v.z), __float2half_rn(w2v.w),
                __float2half_rn(w3.x), __float2half_rn(w3.y), __float2half_rn(w3.z), __float2half_rn(w3.w) };
            *(uint4*)(Bsl)     = ((uint4*)g)[0];
            *(uint4*)(Bsl + 8) = ((uint4*)g)[1];
            __syncthreads();
        }
    }
}

// ---------------- GEMM1: hbuf = relu(gather(x) @ w1[e] + b1[e]) -------------
__global__ __launch_bounds__(256) void gemm1_wmma(
    const float* __restrict__ x, const float* __restrict__ w1, const float* __restrict__ b1)
{
    __shared__ __align__(16) int     toks[128];
    __shared__ __align__(16) __half  Ab[2][128 * ROWP];
    __shared__ __align__(16) __half  Bb[2][KC * BROWP];
    __shared__ __align__(16) float   stg[8][320];

    int e = blockIdx.z;
    int cnt = g_cnt[e];
    int m0 = blockIdx.y * 128;
    if (m0 >= cnt) return;
    int n0 = blockIdx.x * 128;
    int base = g_off[e];

    int tid = threadIdx.x, wid = tid >> 5, lane = tid & 31;
    int warp_m = wid >> 1, warp_n = wid & 1;

    if (tid < 128) {
        int m = m0 + tid;
        toks[tid] = g_row_tok[base + ((m < cnt) ? m : 0)];
    }
    __syncthreads();

    wmma::fragment<wmma::accumulator, 16, 16, 16, float> acc[2][4];
    #pragma unroll
    for (int i = 0; i < 2; i++)
        #pragma unroll
        for (int j = 0; j < 4; j++) wmma::fill_fragment(acc[i][j], 0.f);

    gemm_body<DD, DD / KC, true>(
        x, toks, w1 + (size_t)e * DD * HH + n0, HH,
        Ab[0], Ab[1], Bb[0], Bb[1], nullptr, tid, acc);

    // epilogue: stage through smem, +bias, relu, fp32 store to hbuf
    int erow = lane >> 1, ec8 = (lane & 1) * 8;
    #pragma unroll
    for (int i = 0; i < 2; i++) {
        #pragma unroll
        for (int j = 0; j < 4; j++) {
            wmma::store_matrix_sync(stg[wid], acc[i][j], 20, wmma::mem_row_major);
            __syncwarp();
            int gr = m0 + warp_m * 32 + i * 16 + erow;
            int gc = n0 + warp_n * 64 + j * 16 + ec8;
            if (gr < cnt) {
                float v[8];
                #pragma unroll
                for (int t2 = 0; t2 < 8; t2++)
                    v[t2] = fmaxf(stg[wid][erow * 20 + ec8 + t2]
                                  + b1[(size_t)e * HH + gc + t2], 0.f);
                float* dst = g_hbuf + (size_t)(base + gr) * HH + gc;
                *(float4*)dst       = *(float4*)v;
                *(float4*)(dst + 4) = *(float4*)(v + 4);
            }
            __syncwarp();
        }
    }
}

// ---------------- GEMM2: comb = (hbuf @ w2[e] + b2[e]) * gate ---------------
__global__ __launch_bounds__(256) void gemm2_wmma(
    const float* __restrict__ w2, const float* __restrict__ b2)
{
    __shared__ __align__(16) int     rows[128];
    __shared__ __align__(16) __half  Ab[2][128 * ROWP];
    __shared__ __align__(16) __half  Bb[2][KC * BROWP];
    __shared__ __align__(16) float   stg[8][320];

    int e = blockIdx.z;
    int cnt = g_cnt[e];
    int m0 = blockIdx.y * 128;
    if (m0 >= cnt) return;
    int n0 = blockIdx.x * 128;
    int base = g_off[e];

    int tid = threadIdx.x, wid = tid >> 5, lane = tid & 31;
    int warp_m = wid >> 1, warp_n = wid & 1;

    if (tid < 128) {
        int m = m0 + tid; if (m >= cnt) m = cnt - 1;
        rows[tid] = base + m;
    }
    __syncthreads();

    wmma::fragment<wmma::accumulator, 16, 16, 16, float> acc[2][4];
    #pragma unroll
    for (int i = 0; i < 2; i++)
        #pragma unroll
        for (int j = 0; j < 4; j++) wmma::fill_fragment(acc[i][j], 0.f);

    gemm_body<HH, HH / KC, false>(
        g_hbuf, rows, w2 + (size_t)e * HH * OO + n0, OO,
        Ab[0], Ab[1], Bb[0], Bb[1], nullptr, tid, acc);

    // epilogue: stage, +bias, * gate, fp32 store
    int erow = lane >> 1, ec8 = (lane & 1) * 8;
    #pragma unroll
    for (int i = 0; i < 2; i++) {
        #pragma unroll
        for (int j = 0; j < 4; j++) {
            wmma::store_matrix_sync(stg[wid], acc[i][j], 20, wmma::mem_row_major);
            __syncwarp();
            int gr = m0 + warp_m * 32 + i * 16 + erow;
            int gc = n0 + warp_n * 64 + j * 16 + ec8;
            if (gr < cnt) {
                float gate = g_row_gate[base + gr];
                float v[8];
                #pragma unroll
                for (int t2 = 0; t2 < 8; t2++)
                    v[t2] = (stg[wid][erow * 20 + ec8 + t2] + b2[(size_t)e * OO + gc + t2]) * gate;
                float* dst = g_comb + (size_t)(base + gr) * OO + gc;
                *(float4*)dst       = *(float4*)v;
                *(float4*)(dst + 4) = *(float4*)(v + 4);
            }
            __syncwarp();
        }
    }
}

// ---------------- combine ----------------
__global__ __launch_bounds__(256) void combine_kernel(float* __restrict__ out) {
    int idx = blockIdx.x * blockDim.x + threadIdx.x;
    const int total = TB * OO / 4;
    if (idx >= total) return;
    int t = idx / (OO / 4);
    int c = (idx % (OO / 4)) * 4;
    int r0 = g_tok_row[t * 2 + 0];
    int r1 = g_tok_row[t * 2 + 1];
    float4 a = *(const float4*)(g_comb + (size_t)r0 * OO + c);
    float4 b = *(const float4*)(g_comb + (size_t)r1 * OO + c);
    *(float4*)(out + (size_t)t * OO + c) =
        make_float4(a.x + b.x, a.y + b.y, a.z + b.z, a.w + b.w);
}

// ---------------- launch ----------------
extern "C" void kernel_launch(void* const* d_in, const int* in_sizes, int n_in,
                              void* d_out, int out_size)
{
    const float* x  = (const float*)d_in[0];
    const float* gw = (const float*)d_in[1];
    const float* gb = (const float*)d_in[2];
    const float* w1 = (const float*)d_in[3];
    const float* b1 = (const float*)d_in[4];
    const float* w2 = (const float*)d_in[5];
    const float* b2 = (const float*)d_in[6];
    float* out = (float*)d_out;

    zero_kernel<<<1, 32>>>();
    gate_kernel<<<TB, 256>>>(x, gw, gb);
    offsets_kernel<<<1, 1>>>();
    scatter_kernel<<<TB / 256, 256>>>();
    gemm1_wmma<<<dim3(HH / 128, NR / 128, NE), 256>>>(x, w1, b1);
    gemm2_wmma<<<dim3(OO / 128, NR / 128, NE), 256>>>(w2, b2);
    combine_kernel<<<(TB * OO / 4 + 255) / 256, 256>>>(out);
}